// round 14
// baseline (speedup 1.0000x reference)
#include <cuda_runtime.h>
#include <cuda_fp16.h>
#include <cstdint>

#define HW_  4096
#define C_   256
#define B_   4

// ---------------- scratch (__device__ globals per allocation rules) --------
__device__ __align__(1024) __half g_refT[B_ * HW_ * C_];  // [b*4096+pos][ci]
__device__ __align__(1024) __half g_w[2 * 9 * C_ * C_];   // [w][s][co][ci]
__device__ __align__(1024) __half g_x1t[B_ * HW_ * C_];   // [b*4096+pos][c]
__device__ __align__(1024) __half g_V[B_ * C_ * HW_];     // [b][c][pos]
__device__ __align__(1024) __half g_S[(size_t)B_ * HW_ * HW_]; // scores fp16 [n][m], symmetric
__device__ float g_pmx [B_ * 32 * HW_];   // per-tile-row partial col max
__device__ float g_psum[B_ * 32 * HW_];   // per-tile-row partial col expsum
__device__ float g_mx [B_ * HW_];
__device__ float g_rcp[B_ * HW_];

// ---------------- smem layouts ---------------------------------------------
// scores (128 thr): stage s at s*32768: A +0 (16K), B +16K. 3 stages.
#define SC_SM_A 0
#define SC_SM_B 16384
#define SC_STG  32768
#define SC_NSTG 3
#define SC_SMEM 99328
// conv/av (256 thr): stage s at s*49152: A +0 (32K, 256 rows), B +32K (16K).
#define CV_SM_A 0
#define CV_SM_B 32768
#define CV_STG  49152
#define CV_NSTG 3
#define CV_AUX  147456
#define CV_SMEM 148480

__device__ __forceinline__ uint32_t smem_u32(const void* p) {
    uint32_t a;
    asm("{ .reg .u64 t; cvta.to.shared.u64 t, %1; cvt.u32.u64 %0, t; }" : "=r"(a) : "l"(p));
    return a;
}
#define SW128(o) ((o) ^ (((o) >> 3) & 0x70))

__device__ __forceinline__ void cpa16(uint32_t dst, const void* src) {
    asm volatile("cp.async.cg.shared.global [%0], [%1], 16;" :: "r"(dst), "l"(src));
}
__device__ __forceinline__ void cpa16z(uint32_t dst, const void* src, bool v) {
    int sz = v ? 16 : 0;
    asm volatile("cp.async.cg.shared.global [%0], [%1], 16, %2;" :: "r"(dst), "l"(src), "r"(sz));
}
#define CP_COMMIT() asm volatile("cp.async.commit_group;" ::: "memory")
#define CP_WAIT1()  asm volatile("cp.async.wait_group 1;" ::: "memory")
#define CP_WAIT0()  asm volatile("cp.async.wait_group 0;" ::: "memory")

__device__ __forceinline__ void ldm4(uint32_t r[4], uint32_t addr) {
    asm volatile("ldmatrix.sync.aligned.m8n8.x4.shared.b16 {%0,%1,%2,%3}, [%4];"
        : "=r"(r[0]), "=r"(r[1]), "=r"(r[2]), "=r"(r[3]) : "r"(addr));
}
__device__ __forceinline__ void mma_f16(float d[4], const uint32_t a[4],
                                        uint32_t b0, uint32_t b1) {
    asm volatile("mma.sync.aligned.m16n8k16.row.col.f32.f16.f16.f32 "
        "{%0,%1,%2,%3}, {%4,%5,%6,%7}, {%8,%9}, {%0,%1,%2,%3};"
        : "+f"(d[0]), "+f"(d[1]), "+f"(d[2]), "+f"(d[3])
        : "r"(a[0]), "r"(a[1]), "r"(a[2]), "r"(a[3]), "r"(b0), "r"(b1));
}

// fp16 K=64 chunk on one 64x64 warp tile (4 m-frags x 8 n-frags)
__device__ __forceinline__ void warp_chunk1(float acc[4][8][4],
    uint32_t sA, uint32_t sB, int wm, int wn, int lane)
{
    const int tile = lane >> 3, tr = lane & 7;
    #pragma unroll
    for (int kk = 0; kk < 4; kk++) {
        uint32_t a[4][4];
        #pragma unroll
        for (int mf = 0; mf < 4; mf++) {
            int row = wm + mf * 16 + ((tile & 1) << 3) + tr;
            int g   = 2 * kk + (tile >> 1);
            ldm4(a[mf], sA + SW128((uint32_t)(row * 128 + g * 16)));
        }
        #pragma unroll
        for (int nf = 0; nf < 8; nf += 2) {
            int row = wn + nf * 8 + ((tile >> 1) << 3) + tr;
            int g   = 2 * kk + (tile & 1);
            uint32_t b[4];
            ldm4(b, sB + SW128((uint32_t)(row * 128 + g * 16)));
            #pragma unroll
            for (int mf = 0; mf < 4; mf++) {
                mma_f16(acc[mf][nf],     a[mf], b[0], b[1]);
                mma_f16(acc[mf][nf + 1], a[mf], b[2], b[3]);
            }
        }
    }
}

// accumulators -> fp32 staging st[m*129+n] (wm is LOCAL 0..64)
__device__ __forceinline__ void acc_to_staging(float* st, float acc[4][8][4],
                                               int wm, int wn, int lane, bool relu) {
    const int r0 = lane >> 2, c0 = (lane & 3) * 2;
    #pragma unroll
    for (int mf = 0; mf < 4; mf++)
        #pragma unroll
        for (int nf = 0; nf < 8; nf++)
            #pragma unroll
            for (int i = 0; i < 4; i++) {
                int m = wm + mf * 16 + r0 + (i >> 1) * 8;
                int n = wn + nf * 8 + c0 + (i & 1);
                float v = acc[mf][nf][i];
                st[m * 129 + n] = relu ? fmaxf(v, 0.0f) : v;
            }
}

__device__ __forceinline__ float fast_exp(float x) {
    x = fmaxf(x, -87.0f);
    float y  = x * 1.4426950408889634f;
    float fl = floorf(y);
    float t  = (y - fl) * 0.6931471805599453f;
    float p = 1.3888889e-3f;
    p = fmaf(p, t, 8.3333333e-3f);
    p = fmaf(p, t, 4.1666667e-2f);
    p = fmaf(p, t, 1.6666667e-1f);
    p = fmaf(p, t, 0.5f);
    p = fmaf(p, t, 1.0f);
    p = fmaf(p, t, 1.0f);
    return __int_as_float(((int)fl + 127) << 23) * p;
}
// value as AV will see it (fp16-rounded)
__device__ __forceinline__ float rnd16(float v) {
    return __half2float(__float2half_rn(v));
}

// ---------------- prep: weights -> [w][s][co][ci] fp16 ---------------------
__global__ __launch_bounds__(256) void prep_w_kernel(
    const float* __restrict__ w1, const float* __restrict__ w2)
{
    int idx = blockIdx.x * 256 + threadIdx.x;        // < 1179648
    int w = idx / 589824, r = idx - w * 589824;
    int s = r >> 16, r2 = r & 65535, co = r2 >> 8, ci = r2 & 255;
    const float* wp = w ? w2 : w1;
    g_w[idx] = __float2half_rn(wp[co * 2304 + ci * 9 + s]);
}

// ---------------- prep: ref [b][c][pos] -> refT [b][pos][ci] fp16 ----------
__global__ void prep_refT_kernel(const float* __restrict__ ref)
{
    __shared__ float tile[32][33];
    int b = blockIdx.z, p0 = blockIdx.x * 32, c0 = blockIdx.y * 32;
    int x = threadIdx.x, y = threadIdx.y;            // (32, 8)
    #pragma unroll
    for (int i = 0; i < 4; i++)
        tile[y + i * 8][x] = ref[((size_t)(b * 256 + c0 + y + i * 8)) * 4096 + p0 + x];
    __syncthreads();
    #pragma unroll
    for (int i = 0; i < 4; i++) {
        int p = y + i * 8;
        g_refT[((size_t)((b << 12) + p0 + p)) * 256 + c0 + x] =
            __float2half_rn(tile[x][p]);
    }
}

// ---------------- conv 3x3 SAME + relu: both weights fused -----------------
// grid (32 pos-tiles, 2 co-half, B_). M=256 stacked [w1,w2], N=128 pos.
__global__ __launch_bounds__(256, 1) void conv_mma_kernel()
{
    extern __shared__ char sm[];
    const uint32_t sb = smem_u32(sm);
    const int t = threadIdx.x, lane = t & 31, wid = t >> 5;
    const int wm = (wid & 3) * 64, wn = (wid >> 2) * 64;
    const int pos0 = blockIdx.x * 128;
    const int half = blockIdx.y;
    const int b = blockIdx.z;
    float acc[4][8][4] = {};

    auto do_fill = [&](int kc, int stg) {
        int s = kc >> 2, cc = kc & 3, ci0 = cc * 64;
        int dy = s / 3 - 1, dx = s % 3 - 1, shift = dy * 64 + dx;
        uint32_t base = sb + stg * CV_STG;
        #pragma unroll
        for (int i = 0; i < 8; i++) {
            int idx = t + i * 256, r = idx >> 3, ch = idx & 7;
            int w = r >> 7, co = half * 128 + (r & 127);
            cpa16(base + CV_SM_A + SW128((uint32_t)(r * 128 + ch * 16)),
                  g_w + ((size_t)((w * 9 + s) * 256 + co)) * 256 + ci0 + ch * 8);
        }
        #pragma unroll
        for (int i = 0; i < 4; i++) {
            int idx = t + i * 256, r = idx >> 3, ch = idx & 7;
            int pos = pos0 + r, y = pos >> 6, x = pos & 63;
            int yy = y + dy, xx = x + dx;
            bool valid = ((unsigned)yy < 64u) && ((unsigned)xx < 64u);
            long long so = valid ?
                ((long long)((b << 12) + pos + shift)) * 256 + ci0 + ch * 8 : 0;
            cpa16z(base + CV_SM_B + SW128((uint32_t)(r * 128 + ch * 16)), g_refT + so, valid);
        }
    };

    do_fill(0, 0); CP_COMMIT();
    do_fill(1, 1); CP_COMMIT();
    for (int kc = 0; kc < 36; kc++) {
        CP_WAIT1();
        __syncthreads();
        if (kc + 2 < 36) do_fill(kc + 2, (kc + 2) % CV_NSTG);
        CP_COMMIT();
        uint32_t base = sb + (kc % CV_NSTG) * CV_STG;
        warp_chunk1(acc, base + CV_SM_A, base + CV_SM_B, wm, wn, lane);
    }
    CP_WAIT0();

    // epilogue: relu, pass 0 -> x1t (w1), pass 1 -> V (w2)
    float* st = (float*)sm;
    for (int pass = 0; pass < 2; pass++) {
        __syncthreads();
        if ((wm >> 7) == pass)
            acc_to_staging(st, acc, wm & 127, wn, lane, true);
        __syncthreads();
        if (pass == 0) {
            for (int i = t; i < 16384; i += 256) {
                int p = i >> 7, c = i & 127;      // coalesced over c
                g_x1t[((size_t)((b << 12) + pos0 + p)) * 256 + half * 128 + c] =
                    __float2half_rn(st[c * 129 + p]);
            }
        } else {
            for (int i = t; i < 16384; i += 256) {
                int c = i >> 7, p = i & 127;      // coalesced over p
                g_V[((size_t)((b << 8) + half * 128 + c)) * 4096 + pos0 + p] =
                    __float2half_rn(st[c * 129 + p]);
            }
        }
    }
}

// ---------------- scores = x1t . x1t^T + partial softmax stats -------------
// triangular grid; tile (ti, tj): S rows n0=ti*128, cols m0=tj*128.
__global__ __launch_bounds__(128, 2) void scores_mma_kernel()
{
    extern __shared__ char sm[];
    const uint32_t sb = smem_u32(sm);
    const int t = threadIdx.x, lane = t & 31, wid = t >> 5;
    const int wm = (wid & 1) * 64, wn = (wid >> 1) * 64;
    const int b = blockIdx.y;
    int ti = 0, pp = blockIdx.x;
    while (pp >= 32 - ti) { pp -= 32 - ti; ti++; }
    const int tj = ti + pp;
    const int n0 = ti * 128, m0 = tj * 128;
    float acc[4][8][4] = {};

    auto do_fill = [&](int kc, int stg) {
        int k0 = kc * 64;
        uint32_t base = sb + stg * SC_STG;
        #pragma unroll
        for (int ii2 = 0; ii2 < 8; ii2++) {
            int idx = t + ii2 * 128, r = idx >> 3, ch = idx & 7;
            uint32_t sw = SW128((uint32_t)(r * 128 + ch * 16));
            cpa16(base + SC_SM_A + sw,
                  g_x1t + ((size_t)((b << 12) + n0 + r)) * 256 + k0 + ch * 8);
            cpa16(base + SC_SM_B + sw,
                  g_x1t + ((size_t)((b << 12) + m0 + r)) * 256 + k0 + ch * 8);
        }
    };

    do_fill(0, 0); CP_COMMIT();
    do_fill(1, 1); CP_COMMIT();
    for (int kc = 0; kc < 4; kc++) {
        CP_WAIT1();
        __syncthreads();
        if (kc + 2 < 4) do_fill(kc + 2, (kc + 2) % SC_NSTG);
        CP_COMMIT();
        uint32_t base = sb + (kc % SC_NSTG) * SC_STG;
        warp_chunk1(acc, base + SC_SM_A, base + SC_SM_B, wm, wn, lane);
    }
    CP_WAIT0();
    __syncthreads();

    float* st = (float*)sm;
    acc_to_staging(st, acc, wm, wn, lane, false);
    __syncthreads();
    __half* Sb = g_S + (size_t)b * HW_ * HW_;
    for (int ii2 = t; ii2 < 16384; ii2 += 128) {
        int r = ii2 >> 7, c = ii2 & 127;
        Sb[(size_t)(n0 + r) * 4096 + m0 + c] = __float2half_rn(st[r * 129 + c]);
    }
    if (n0 != m0) {
        for (int ii2 = t; ii2 < 16384; ii2 += 128) {
            int r = ii2 >> 7, c = ii2 & 127;
            Sb[(size_t)(m0 + r) * 4096 + n0 + c] = __float2half_rn(st[c * 129 + r]);
        }
    }

    // partial column stats over this tile's 128 rows (values fp16-rounded,
    // matching what AV will exponentiate). Thread t owns column t.
    {
        float mx = -1e30f;
        #pragma unroll 8
        for (int r = 0; r < 128; r++)
            mx = fmaxf(mx, rnd16(st[r * 129 + t]));
        float s = 0.0f;
        #pragma unroll 4
        for (int r = 0; r < 128; r++)
            s += fast_exp(rnd16(st[r * 129 + t]) - mx);
        g_pmx [((b * 32 + ti) << 12) + m0 + t] = mx;
        g_psum[((b * 32 + ti) << 12) + m0 + t] = s;
    }
    // mirror tile: columns n0.. over rows tj -> row stats of staging
    if (n0 != m0) {
        float mx = -1e30f;
        #pragma unroll 8
        for (int c = 0; c < 128; c++)
            mx = fmaxf(mx, rnd16(st[t * 129 + c]));
        float s = 0.0f;
        #pragma unroll 4
        for (int c = 0; c < 128; c++)
            s += fast_exp(rnd16(st[t * 129 + c]) - mx);
        g_pmx [((b * 32 + tj) << 12) + n0 + t] = mx;
        g_psum[((b * 32 + tj) << 12) + n0 + t] = s;
    }
}

// ---------------- combine partial stats -> g_mx, g_rcp ---------------------
__global__ __launch_bounds__(256) void stats_reduce_kernel()
{
    int b = blockIdx.y, m = blockIdx.x * 256 + threadIdx.x;
    float mx = -1e30f;
    #pragma unroll
    for (int i = 0; i < 32; i++)
        mx = fmaxf(mx, g_pmx[((b * 32 + i) << 12) + m]);
    float s = 0.0f;
    #pragma unroll
    for (int i = 0; i < 32; i++)
        s += g_psum[((b * 32 + i) << 12) + m] *
             fast_exp(g_pmx[((b * 32 + i) << 12) + m] - mx);
    g_mx [(b << 12) + m] = mx;
    g_rcp[(b << 12) + m] = 1.0f / s;
}

// ---------------- AV: out = gamma * rcp[m] * (V . E^T) + ref ---------------
// grid (32 m-tiles, B_). E computed inline: B tile = exp(S[m][n] - mx[m]).
__global__ __launch_bounds__(256, 1) void av_mma_kernel(
    const float* __restrict__ ref, const float* __restrict__ gamma_p,
    float* __restrict__ out)
{
    extern __shared__ char sm[];
    const uint32_t sb = smem_u32(sm);
    const int t = threadIdx.x, lane = t & 31, wid = t >> 5;
    const int wm = (wid & 3) * 64, wn = (wid >> 2) * 64;
    const int m0 = blockIdx.x * 128, b = blockIdx.y;
    float* s_mx = (float*)(sm + CV_AUX);
    float* s_rc = (float*)(sm + CV_AUX + 512);
    if (t < 128) {
        s_mx[t] = g_mx[(b << 12) + m0 + t];
        s_rc[t] = (*gamma_p) * g_rcp[(b << 12) + m0 + t];
    }
    float acc[4][8][4] = {};

    auto do_fill = [&](int kc, int stg) {
        int k0 = kc * 64;
        uint32_t base = sb + stg * CV_STG;
        #pragma unroll
        for (int i = 0; i < 8; i++) {
            int idx = t + i * 256, r = idx >> 3, ch = idx & 7;
            cpa16(base + CV_SM_A + SW128((uint32_t)(r * 128 + ch * 16)),
                  g_V + ((size_t)((b << 8) + r)) * 4096 + k0 + ch * 8);
        }
        #pragma unroll
        for (int i = 0; i < 4; i++) {
            int idx = t + i * 256, r = idx >> 3, ch = idx & 7;
            cpa16(base + CV_SM_B + SW128((uint32_t)(r * 128 + ch * 16)),
                  g_S + ((size_t)b * HW_ + m0 + r) * 4096 + k0 + ch * 8);
        }
    };

    do_fill(0, 0); CP_COMMIT();
    do_fill(1, 1); CP_COMMIT();
    for (int kc = 0; kc < 64; kc++) {
        CP_WAIT1();
        __syncthreads();
        if (kc + 2 < 64) do_fill(kc + 2, (kc + 2) % CV_NSTG);
        CP_COMMIT();
        // in-place exp on this stage's B (S -> E). Swizzle keeps row = off>>7.
        char* stp = sm + (kc % CV_NSTG) * CV_STG + CV_SM_B;
        #pragma unroll
        for (int i = 0; i < 4; i++) {
            uint32_t off = (uint32_t)(t + i * 256) * 16;
            float mxr = s_mx[off >> 7];
            union { uint4 u; __half h[8]; } x;
            x.u = *(uint4*)(stp + off);
            #pragma unroll
            for (int j = 0; j < 8; j++)
                x.h[j] = __float2half_rn(fast_exp(__half2float(x.h[j]) - mxr));
            *(uint4*)(stp + off) = x.u;
        }
        __syncthreads();
        uint32_t base = sb + (kc % CV_NSTG) * CV_STG;
        warp_chunk1(acc, base + CV_SM_A, base + CV_SM_B, wm, wn, lane);
    }
    CP_WAIT0();

    // epilogue: two c-half passes through staging (preserve s_rc in AUX)
    float* st = (float*)sm;
    for (int pass = 0; pass < 2; pass++) {
        __syncthreads();
        if ((wm >> 7) == pass)
            acc_to_staging(st, acc, wm & 127, wn, lane, false);
        __syncthreads();
        for (int ii2 = t; ii2 < 16384; ii2 += 256) {
            int cl = ii2 >> 7, n = ii2 & 127;     // coalesced over n
            size_t o = ((size_t)((b << 8) + pass * 128 + cl)) * 4096 + m0 + n;
            out[o] = fmaf(st[cl * 129 + n], s_rc[n], ref[o]);
        }
    }
}

// ---------------------------------------------------------------------------
extern "C" void kernel_launch(void* const* d_in, const int* in_sizes, int n_in,
                              void* d_out, int out_size)
{
    const float* ref   = (const float*)d_in[1];   // d_in[0] 'inputs' is dead in reference
    const float* w1    = (const float*)d_in[2];
    const float* w2    = (const float*)d_in[3];
    const float* gamma = (const float*)d_in[4];
    float* out = (float*)d_out;

    cudaFuncSetAttribute(conv_mma_kernel,   cudaFuncAttributeMaxDynamicSharedMemorySize, CV_SMEM);
    cudaFuncSetAttribute(scores_mma_kernel, cudaFuncAttributeMaxDynamicSharedMemorySize, SC_SMEM);
    cudaFuncSetAttribute(av_mma_kernel,     cudaFuncAttributeMaxDynamicSharedMemorySize, CV_SMEM);

    prep_w_kernel<<<4608, 256>>>(w1, w2);
    prep_refT_kernel<<<dim3(128, 8, B_), dim3(32, 8)>>>(ref);
    conv_mma_kernel<<<dim3(32, 2, B_), 256, CV_SMEM>>>();
    scores_mma_kernel<<<dim3(528, B_), 128, SC_SMEM>>>();
    stats_reduce_kernel<<<dim3(16, B_), 256>>>();
    av_mma_kernel<<<dim3(32, B_), 256, CV_SMEM>>>(ref, gamma, out);
}

// round 16
// speedup vs baseline: 1.1847x; 1.1847x over previous
#include <cuda_runtime.h>
#include <cuda_fp16.h>
#include <cstdint>

#define HW_  4096
#define C_   256
#define B_   4

// ---------------- scratch (__device__ globals per allocation rules) --------
__device__ __align__(1024) __half g_refT[B_ * HW_ * C_];  // [b*4096+pos][ci]
__device__ __align__(1024) __half g_w[2 * 9 * C_ * C_];   // [w][s][co][ci]
__device__ __align__(1024) __half g_x1t[B_ * HW_ * C_];   // [b*4096+pos][c]
__device__ __align__(1024) __half g_V[B_ * C_ * HW_];     // [b][c][pos]
__device__ __align__(1024) __half g_E[(size_t)B_ * HW_ * HW_]; // exp(S-mx) [m][n]
__device__ __align__(1024) __half g_S[(size_t)B_ * HW_ * HW_]; // scores fp16 [n][m]
__device__ float g_rcp[B_ * HW_];

// ---------------- smem layouts ---------------------------------------------
// scores (128 thr): A resident 4 strips @0 (64K); B 2 stages @65536 (16K each).
#define SC_SM_B  65536
#define SC_BSTG  16384
#define SC_SMEM  98304
// conv/av (256 thr): stage s at s*49152: A +0 (32K, 256 rows), B +32K (16K).
#define CV_SM_A 0
#define CV_SM_B 32768
#define CV_STG  49152
#define CV_NSTG 3
#define CV_AUX  147456
#define CV_SMEM 148480

__device__ __forceinline__ uint32_t smem_u32(const void* p) {
    uint32_t a;
    asm("{ .reg .u64 t; cvta.to.shared.u64 t, %1; cvt.u32.u64 %0, t; }" : "=r"(a) : "l"(p));
    return a;
}
#define SW128(o) ((o) ^ (((o) >> 3) & 0x70))

__device__ __forceinline__ void cpa16(uint32_t dst, const void* src) {
    asm volatile("cp.async.cg.shared.global [%0], [%1], 16;" :: "r"(dst), "l"(src));
}
__device__ __forceinline__ void cpa16z(uint32_t dst, const void* src, bool v) {
    int sz = v ? 16 : 0;
    asm volatile("cp.async.cg.shared.global [%0], [%1], 16, %2;" :: "r"(dst), "l"(src), "r"(sz));
}
#define CP_COMMIT() asm volatile("cp.async.commit_group;" ::: "memory")
#define CP_WAIT1()  asm volatile("cp.async.wait_group 1;" ::: "memory")
#define CP_WAIT0()  asm volatile("cp.async.wait_group 0;" ::: "memory")

__device__ __forceinline__ void ldm4(uint32_t r[4], uint32_t addr) {
    asm volatile("ldmatrix.sync.aligned.m8n8.x4.shared.b16 {%0,%1,%2,%3}, [%4];"
        : "=r"(r[0]), "=r"(r[1]), "=r"(r[2]), "=r"(r[3]) : "r"(addr));
}
__device__ __forceinline__ void mma_f16(float d[4], const uint32_t a[4],
                                        uint32_t b0, uint32_t b1) {
    asm volatile("mma.sync.aligned.m16n8k16.row.col.f32.f16.f16.f32 "
        "{%0,%1,%2,%3}, {%4,%5,%6,%7}, {%8,%9}, {%0,%1,%2,%3};"
        : "+f"(d[0]), "+f"(d[1]), "+f"(d[2]), "+f"(d[3])
        : "r"(a[0]), "r"(a[1]), "r"(a[2]), "r"(a[3]), "r"(b0), "r"(b1));
}

// fp16 K=64 chunk on one 64x64 warp tile (4 m-frags x 8 n-frags)
__device__ __forceinline__ void warp_chunk1(float acc[4][8][4],
    uint32_t sA, uint32_t sB, int wm, int wn, int lane)
{
    const int tile = lane >> 3, tr = lane & 7;
    #pragma unroll
    for (int kk = 0; kk < 4; kk++) {
        uint32_t a[4][4];
        #pragma unroll
        for (int mf = 0; mf < 4; mf++) {
            int row = wm + mf * 16 + ((tile & 1) << 3) + tr;
            int g   = 2 * kk + (tile >> 1);
            ldm4(a[mf], sA + SW128((uint32_t)(row * 128 + g * 16)));
        }
        #pragma unroll
        for (int nf = 0; nf < 8; nf += 2) {
            int row = wn + nf * 8 + ((tile >> 1) << 3) + tr;
            int g   = 2 * kk + (tile & 1);
            uint32_t b[4];
            ldm4(b, sB + SW128((uint32_t)(row * 128 + g * 16)));
            #pragma unroll
            for (int mf = 0; mf < 4; mf++) {
                mma_f16(acc[mf][nf],     a[mf], b[0], b[1]);
                mma_f16(acc[mf][nf + 1], a[mf], b[2], b[3]);
            }
        }
    }
}

// accumulators -> fp32 staging st[m*129+n] (wm is LOCAL 0..64)
__device__ __forceinline__ void acc_to_staging(float* st, float acc[4][8][4],
                                               int wm, int wn, int lane, bool relu) {
    const int r0 = lane >> 2, c0 = (lane & 3) * 2;
    #pragma unroll
    for (int mf = 0; mf < 4; mf++)
        #pragma unroll
        for (int nf = 0; nf < 8; nf++)
            #pragma unroll
            for (int i = 0; i < 4; i++) {
                int m = wm + mf * 16 + r0 + (i >> 1) * 8;
                int n = wn + nf * 8 + c0 + (i & 1);
                float v = acc[mf][nf][i];
                st[m * 129 + n] = relu ? fmaxf(v, 0.0f) : v;
            }
}

__device__ __forceinline__ float fast_exp(float x) {
    x = fmaxf(x, -87.0f);
    float y  = x * 1.4426950408889634f;
    float fl = floorf(y);
    float t  = (y - fl) * 0.6931471805599453f;
    float p = 1.3888889e-3f;
    p = fmaf(p, t, 8.3333333e-3f);
    p = fmaf(p, t, 4.1666667e-2f);
    p = fmaf(p, t, 1.6666667e-1f);
    p = fmaf(p, t, 0.5f);
    p = fmaf(p, t, 1.0f);
    p = fmaf(p, t, 1.0f);
    return __int_as_float(((int)fl + 127) << 23) * p;
}

// ---------------- prep: weights -> [w][s][co][ci] fp16 ---------------------
__global__ __launch_bounds__(256) void prep_w_kernel(
    const float* __restrict__ w1, const float* __restrict__ w2)
{
    int idx = blockIdx.x * 256 + threadIdx.x;        // < 1179648
    int w = idx / 589824, r = idx - w * 589824;
    int s = r >> 16, r2 = r & 65535, co = r2 >> 8, ci = r2 & 255;
    const float* wp = w ? w2 : w1;
    g_w[idx] = __float2half_rn(wp[co * 2304 + ci * 9 + s]);
}

// ---------------- prep: ref [b][c][pos] -> refT [b][pos][ci] fp16 ----------
__global__ void prep_refT_kernel(const float* __restrict__ ref)
{
    __shared__ float tile[32][33];
    int b = blockIdx.z, p0 = blockIdx.x * 32, c0 = blockIdx.y * 32;
    int x = threadIdx.x, y = threadIdx.y;            // (32, 8)
    #pragma unroll
    for (int i = 0; i < 4; i++)
        tile[y + i * 8][x] = ref[((size_t)(b * 256 + c0 + y + i * 8)) * 4096 + p0 + x];
    __syncthreads();
    #pragma unroll
    for (int i = 0; i < 4; i++) {
        int p = y + i * 8;
        g_refT[((size_t)((b << 12) + p0 + p)) * 256 + c0 + x] =
            __float2half_rn(tile[x][p]);
    }
}

// ---------------- conv 3x3 SAME + relu: both weights fused -----------------
// grid (32 pos-tiles, 2 co-half, B_). M=256 stacked [w1,w2], N=128 pos.
__global__ __launch_bounds__(256, 1) void conv_mma_kernel()
{
    extern __shared__ char sm[];
    const uint32_t sb = smem_u32(sm);
    const int t = threadIdx.x, lane = t & 31, wid = t >> 5;
    const int wm = (wid & 3) * 64, wn = (wid >> 2) * 64;
    const int pos0 = blockIdx.x * 128;
    const int half = blockIdx.y;
    const int b = blockIdx.z;
    float acc[4][8][4] = {};

    auto do_fill = [&](int kc, int stg) {
        int s = kc >> 2, cc = kc & 3, ci0 = cc * 64;
        int dy = s / 3 - 1, dx = s % 3 - 1, shift = dy * 64 + dx;
        uint32_t base = sb + stg * CV_STG;
        #pragma unroll
        for (int i = 0; i < 8; i++) {
            int idx = t + i * 256, r = idx >> 3, ch = idx & 7;
            int w = r >> 7, co = half * 128 + (r & 127);
            cpa16(base + CV_SM_A + SW128((uint32_t)(r * 128 + ch * 16)),
                  g_w + ((size_t)((w * 9 + s) * 256 + co)) * 256 + ci0 + ch * 8);
        }
        #pragma unroll
        for (int i = 0; i < 4; i++) {
            int idx = t + i * 256, r = idx >> 3, ch = idx & 7;
            int pos = pos0 + r, y = pos >> 6, x = pos & 63;
            int yy = y + dy, xx = x + dx;
            bool valid = ((unsigned)yy < 64u) && ((unsigned)xx < 64u);
            long long so = valid ?
                ((long long)((b << 12) + pos + shift)) * 256 + ci0 + ch * 8 : 0;
            cpa16z(base + CV_SM_B + SW128((uint32_t)(r * 128 + ch * 16)), g_refT + so, valid);
        }
    };

    do_fill(0, 0); CP_COMMIT();
    do_fill(1, 1); CP_COMMIT();
    for (int kc = 0; kc < 36; kc++) {
        CP_WAIT1();
        __syncthreads();
        if (kc + 2 < 36) do_fill(kc + 2, (kc + 2) % CV_NSTG);
        CP_COMMIT();
        uint32_t base = sb + (kc % CV_NSTG) * CV_STG;
        warp_chunk1(acc, base + CV_SM_A, base + CV_SM_B, wm, wn, lane);
    }
    CP_WAIT0();

    // epilogue: relu, pass 0 -> x1t (w1), pass 1 -> V (w2)
    float* st = (float*)sm;
    for (int pass = 0; pass < 2; pass++) {
        __syncthreads();
        if ((wm >> 7) == pass)
            acc_to_staging(st, acc, wm & 127, wn, lane, true);
        __syncthreads();
        if (pass == 0) {
            for (int i = t; i < 16384; i += 256) {
                int p = i >> 7, c = i & 127;      // coalesced over c
                g_x1t[((size_t)((b << 12) + pos0 + p)) * 256 + half * 128 + c] =
                    __float2half_rn(st[c * 129 + p]);
            }
        } else {
            for (int i = t; i < 16384; i += 256) {
                int c = i >> 7, p = i & 127;      // coalesced over p
                g_V[((size_t)((b << 8) + half * 128 + c)) * 4096 + pos0 + p] =
                    __float2half_rn(st[c * 129 + p]);
            }
        }
    }
}

// ---------------- scores = x1t . x1t^T (symmetric, triangular grid) --------
// A (n-tile) fully resident (4 K-strips); B (m-tile) 2-stage, prefetch dist 1.
__global__ __launch_bounds__(128, 2) void scores_mma_kernel()
{
    extern __shared__ char sm[];
    const uint32_t sb = smem_u32(sm);
    const int t = threadIdx.x, lane = t & 31, wid = t >> 5;
    const int wm = (wid & 1) * 64, wn = (wid >> 1) * 64;
    const int b = blockIdx.y;
    int i = 0, pp = blockIdx.x;
    while (pp >= 32 - i) { pp -= 32 - i; i++; }
    const int n0 = i * 128, m0 = (i + pp) * 128;
    float acc[4][8][4] = {};

    auto fill_b = [&](int kc, int stg) {
        int k0 = kc * 64;
        uint32_t base = sb + SC_SM_B + stg * SC_BSTG;
        #pragma unroll
        for (int ii2 = 0; ii2 < 8; ii2++) {
            int idx = t + ii2 * 128, r = idx >> 3, ch = idx & 7;
            cpa16(base + SW128((uint32_t)(r * 128 + ch * 16)),
                  g_x1t + ((size_t)((b << 12) + m0 + r)) * 256 + k0 + ch * 8);
        }
    };

    // prologue: A resident (all 4 strips) + B chunk 0 in one group
    #pragma unroll
    for (int st4 = 0; st4 < 4; st4++) {
        #pragma unroll
        for (int ii2 = 0; ii2 < 8; ii2++) {
            int idx = t + ii2 * 128, r = idx >> 3, ch = idx & 7;
            cpa16(sb + st4 * 16384 + SW128((uint32_t)(r * 128 + ch * 16)),
                  g_x1t + ((size_t)((b << 12) + n0 + r)) * 256 + st4 * 64 + ch * 8);
        }
    }
    fill_b(0, 0); CP_COMMIT();
    // steady state: wait all, prefetch kc+1 into the OTHER stage, compute kc
    for (int kc = 0; kc < 4; kc++) {
        CP_WAIT0();
        __syncthreads();
        if (kc + 1 < 4) { fill_b(kc + 1, (kc + 1) & 1); CP_COMMIT(); }
        warp_chunk1(acc, sb + kc * 16384, sb + SC_SM_B + (kc & 1) * SC_BSTG,
                    wm, wn, lane);
    }
    CP_WAIT0();
    __syncthreads();

    float* st = (float*)sm;
    acc_to_staging(st, acc, wm, wn, lane, false);
    __syncthreads();
    __half* Sb = g_S + (size_t)b * HW_ * HW_;
    for (int ii2 = t; ii2 < 16384; ii2 += 128) {
        int r = ii2 >> 7, c = ii2 & 127;
        Sb[(size_t)(n0 + r) * 4096 + m0 + c] = __float2half_rn(st[r * 129 + c]);
    }
    if (n0 != m0) {
        for (int ii2 = t; ii2 < 16384; ii2 += 128) {
            int r = ii2 >> 7, c = ii2 & 127;
            Sb[(size_t)(m0 + r) * 4096 + n0 + c] = __float2half_rn(st[c * 129 + r]);
        }
    }
}

// ---------------- row stats + E materialization (fp16 S in, fp16 E out) ----
__global__ __launch_bounds__(256) void rowstats_kernel()
{
    __shared__ float red[256];
    const int b = blockIdx.y, m = blockIdx.x, t = threadIdx.x;
    const __half* __restrict__ row = g_S + ((size_t)b * HW_ + m) * HW_;

    union { uint4 u; __half h[8]; } cv[2];
    float v[16];
    #pragma unroll
    for (int i = 0; i < 2; i++) {
        cv[i].u = ((const uint4*)row)[t + i * 256];
        #pragma unroll
        for (int j = 0; j < 8; j++) v[i * 8 + j] = __half2float(cv[i].h[j]);
    }
    float mx = -1e30f;
    #pragma unroll
    for (int i = 0; i < 16; i++) mx = fmaxf(mx, v[i]);
    red[t] = mx;
    __syncthreads();
    #pragma unroll
    for (int s = 128; s >= 32; s >>= 1) {
        if (t < s) red[t] = fmaxf(red[t], red[t + s]);
        __syncthreads();
    }
    if (t < 32) {
        float r = red[t];
        #pragma unroll
        for (int o = 16; o > 0; o >>= 1) r = fmaxf(r, __shfl_xor_sync(~0u, r, o));
        red[0] = r;
    }
    __syncthreads();
    mx = red[0];
    __syncthreads();
    float sum = 0.0f;
    #pragma unroll
    for (int i = 0; i < 2; i++) {
        union { uint4 u; __half h[8]; } ev;
        #pragma unroll
        for (int j = 0; j < 8; j++) {
            float e = fast_exp(v[i * 8 + j] - mx);
            sum += e;
            ev.h[j] = __float2half_rn(e);
        }
        ((uint4*)(g_E + ((size_t)((b << 12) + m)) * 4096))[t + i * 256] = ev.u;
    }
    red[t] = sum;
    __syncthreads();
    #pragma unroll
    for (int s = 128; s >= 32; s >>= 1) {
        if (t < s) red[t] += red[t + s];
        __syncthreads();
    }
    if (t < 32) {
        float r = red[t];
        #pragma unroll
        for (int o = 16; o > 0; o >>= 1) r += __shfl_xor_sync(~0u, r, o);
        if (t == 0) g_rcp[b * HW_ + m] = 1.0f / r;
    }
}

// ---------------- AV: out = gamma * rcp[m] * (V . E^T) + ref ---------------
// grid (32 m-tiles, B_). M=256 (all c), N=128 m, K = n (4096). E read ONCE.
__global__ __launch_bounds__(256, 1) void av_mma_kernel(
    const float* __restrict__ ref, const float* __restrict__ gamma_p,
    float* __restrict__ out)
{
    extern __shared__ char sm[];
    const uint32_t sb = smem_u32(sm);
    const int t = threadIdx.x, lane = t & 31, wid = t >> 5;
    const int wm = (wid & 3) * 64, wn = (wid >> 2) * 64;
    const int m0 = blockIdx.x * 128, b = blockIdx.y;
    float acc[4][8][4] = {};

    auto do_fill = [&](int kc, int stg) {
        int k0 = kc * 64;
        uint32_t base = sb + stg * CV_STG;
        #pragma unroll
        for (int i = 0; i < 8; i++) {
            int idx = t + i * 256, r = idx >> 3, ch = idx & 7;
            cpa16(base + CV_SM_A + SW128((uint32_t)(r * 128 + ch * 16)),
                  g_V + ((size_t)((b << 8) + r)) * 4096 + k0 + ch * 8);
        }
        #pragma unroll
        for (int i = 0; i < 4; i++) {
            int idx = t + i * 256, r = idx >> 3, ch = idx & 7;
            cpa16(base + CV_SM_B + SW128((uint32_t)(r * 128 + ch * 16)),
                  g_E + ((size_t)((b << 12) + m0 + r)) * 4096 + k0 + ch * 8);
        }
    };

    do_fill(0, 0); CP_COMMIT();
    do_fill(1, 1); CP_COMMIT();
    for (int kc = 0; kc < 64; kc++) {
        CP_WAIT1();
        __syncthreads();
        if (kc + 2 < 64) do_fill(kc + 2, (kc + 2) % CV_NSTG);
        CP_COMMIT();
        uint32_t base = sb + (kc % CV_NSTG) * CV_STG;
        warp_chunk1(acc, base + CV_SM_A, base + CV_SM_B, wm, wn, lane);
    }
    CP_WAIT0();

    // epilogue: two c-half passes through staging
    float* st = (float*)sm;
    float* s_rc = (float*)(sm + CV_AUX);
    if (t < 128) s_rc[t] = (*gamma_p) * g_rcp[(b << 12) + m0 + t];
    for (int pass = 0; pass < 2; pass++) {
        __syncthreads();
        if ((wm >> 7) == pass)
            acc_to_staging(st, acc, wm & 127, wn, lane, false);
        __syncthreads();
        for (int ii2 = t; ii2 < 16384; ii2 += 256) {
            int cl = ii2 >> 7, n = ii2 & 127;     // coalesced over n
            size_t o = ((size_t)((b << 8) + pass * 128 + cl)) * 4096 + m0 + n;
            out[o] = fmaf(st[cl * 129 + n], s_rc[n], ref[o]);
        }
    }
}

// ---------------------------------------------------------------------------
extern "C" void kernel_launch(void* const* d_in, const int* in_sizes, int n_in,
                              void* d_out, int out_size)
{
    const float* ref   = (const float*)d_in[1];   // d_in[0] 'inputs' is dead in reference
    const float* w1    = (const float*)d_in[2];
    const float* w2    = (const float*)d_in[3];
    const float* gamma = (const float*)d_in[4];
    float* out = (float*)d_out;

    cudaFuncSetAttribute(conv_mma_kernel,   cudaFuncAttributeMaxDynamicSharedMemorySize, CV_SMEM);
    cudaFuncSetAttribute(scores_mma_kernel, cudaFuncAttributeMaxDynamicSharedMemorySize, SC_SMEM);
    cudaFuncSetAttribute(av_mma_kernel,     cudaFuncAttributeMaxDynamicSharedMemorySize, CV_SMEM);

    prep_w_kernel<<<4608, 256>>>(w1, w2);
    prep_refT_kernel<<<dim3(128, 8, B_), dim3(32, 8)>>>(ref);
    conv_mma_kernel<<<dim3(32, 2, B_), 256, CV_SMEM>>>();
    scores_mma_kernel<<<dim3(528, B_), 128, SC_SMEM>>>();
    rowstats_kernel<<<dim3(4096, B_), 256>>>();
    av_mma_kernel<<<dim3(32, B_), 256, CV_SMEM>>>(ref, gamma, out);
}